// round 2
// baseline (speedup 1.0000x reference)
#include <cuda_runtime.h>
#include <math.h>
#include <stdint.h>

#define NN 50000
#define NE 800000
#define NBLK ((NN + 1023) / 1024)   // 49 scan blocks

// ---------------- scratch (static device globals; no allocation) -------------
__device__ int   g_cnt[NN];
__device__ int   g_rowptr[NN + 1];
__device__ int   g_cursor[NN];
__device__ int   g_colsrc[NE];
__device__ int   g_bsum[64];
__device__ float g_dinv[NN];
__device__ float g_h32 [(size_t)NN * 32];
__device__ float g_h64 [(size_t)NN * 64];
__device__ float g_h128[(size_t)NN * 128];
__device__ float g_p128[(size_t)NN * 128];
__device__ float g_h256[(size_t)NN * 256];
__device__ float g_p256[(size_t)NN * 256];
__device__ float g_h512[(size_t)NN * 512];
__device__ float g_t64 [(size_t)NN * 64];
__device__ float g_p64 [(size_t)NN * 64];

// ---------------- degree / CSR build -----------------------------------------
__global__ void k_zero_cnt() {
    int i = blockIdx.x * blockDim.x + threadIdx.x;
    if (i < NN) g_cnt[i] = 0;
}

// edge_index is int32 (JAX x64 disabled downgrades int64 -> int32)
__global__ void k_count(const int* __restrict__ ei) {
    int e = blockIdx.x * blockDim.x + threadIdx.x;
    if (e < NE) {
        int dst = ei[NE + e];
        if ((unsigned)dst < NN) atomicAdd(&g_cnt[dst], 1);
    }
}

__global__ void k_dinv() {
    int i = blockIdx.x * blockDim.x + threadIdx.x;
    if (i < NN) g_dinv[i] = rsqrtf((float)g_cnt[i] + 1.0f);
}

__global__ void k_scan1() {
    __shared__ int sh[1024];
    int tid = threadIdx.x;
    int i = blockIdx.x * 1024 + tid;
    int v = (i < NN) ? g_cnt[i] : 0;
    sh[tid] = v;
    __syncthreads();
    for (int off = 1; off < 1024; off <<= 1) {
        int t = (tid >= off) ? sh[tid - off] : 0;
        __syncthreads();
        sh[tid] += t;
        __syncthreads();
    }
    if (i < NN) g_rowptr[i] = sh[tid] - v;   // exclusive within block
    if (tid == 1023) g_bsum[blockIdx.x] = sh[1023];
}

__global__ void k_scan2() {
    __shared__ int sh[64];
    int tid = threadIdx.x;
    int v = (tid < NBLK) ? g_bsum[tid] : 0;
    sh[tid] = v;
    __syncthreads();
    for (int off = 1; off < 64; off <<= 1) {
        int t = (tid >= off) ? sh[tid - off] : 0;
        __syncthreads();
        sh[tid] += t;
        __syncthreads();
    }
    g_bsum[tid] = sh[tid] - v;   // exclusive
}

__global__ void k_scan3() {
    int i = blockIdx.x * blockDim.x + threadIdx.x;
    if (i < NN) {
        int r = g_rowptr[i] + g_bsum[i >> 10];
        g_rowptr[i] = r;
        g_cursor[i] = r;
    }
    if (i == 0) g_rowptr[NN] = NE;
}

__global__ void k_scatter(const int* __restrict__ ei) {
    int e = blockIdx.x * blockDim.x + threadIdx.x;
    if (e < NE) {
        int dst = ei[NE + e];
        int src = ei[e];
        if ((unsigned)dst < NN && (unsigned)src < NN) {
            int pos = atomicAdd(&g_cursor[dst], 1);
            if ((unsigned)pos < NE) g_colsrc[pos] = src;
        }
    }
}

// ---------------- generic tiled fp32 GEMM: C = act(A @ W + bias) --------------
// A: [M,K] row-major, W: [K,Ntrue] row-major, C: [M,Npad] (cols >= Ntrue set 0)
__global__ __launch_bounds__(256)
void k_gemm(const float* __restrict__ A, const float* __restrict__ W,
            const float* __restrict__ bias, float* __restrict__ C,
            int M, int K, int Ntrue, int Npad, int relu) {
    constexpr int BM = 64, BN = 64, BK = 16;
    __shared__ float sA[BK][BM + 1];
    __shared__ float sB[BK][BN];
    int tid = threadIdx.x;
    int tx = tid & 15;   // col group (4 cols each)
    int ty = tid >> 4;   // row group (4 rows each)
    int bm0 = blockIdx.x * BM;
    int bn0 = blockIdx.y * BN;

    float acc[4][4];
#pragma unroll
    for (int i = 0; i < 4; i++)
#pragma unroll
        for (int j = 0; j < 4; j++) acc[i][j] = 0.f;

    for (int k0 = 0; k0 < K; k0 += BK) {
#pragma unroll
        for (int i = 0; i < 4; i++) {             // A tile 64x16
            int idx = tid + i * 256;
            int r = idx >> 4, kk = idx & 15;
            int gr = bm0 + r, gk = k0 + kk;
            sA[kk][r] = (gr < M && gk < K) ? A[(size_t)gr * K + gk] : 0.f;
        }
#pragma unroll
        for (int i = 0; i < 4; i++) {             // W tile 16x64
            int idx = tid + i * 256;
            int kk = idx >> 6, nn = idx & 63;
            int gk = k0 + kk, gn = bn0 + nn;
            sB[kk][nn] = (gk < K && gn < Ntrue) ? W[(size_t)gk * Ntrue + gn] : 0.f;
        }
        __syncthreads();
#pragma unroll
        for (int kk = 0; kk < BK; kk++) {
            float a0 = sA[kk][ty * 4 + 0];
            float a1 = sA[kk][ty * 4 + 1];
            float a2 = sA[kk][ty * 4 + 2];
            float a3 = sA[kk][ty * 4 + 3];
            float4 b = *(const float4*)&sB[kk][tx * 4];
            acc[0][0] += a0 * b.x; acc[0][1] += a0 * b.y; acc[0][2] += a0 * b.z; acc[0][3] += a0 * b.w;
            acc[1][0] += a1 * b.x; acc[1][1] += a1 * b.y; acc[1][2] += a1 * b.z; acc[1][3] += a1 * b.w;
            acc[2][0] += a2 * b.x; acc[2][1] += a2 * b.y; acc[2][2] += a2 * b.z; acc[2][3] += a2 * b.w;
            acc[3][0] += a3 * b.x; acc[3][1] += a3 * b.y; acc[3][2] += a3 * b.z; acc[3][3] += a3 * b.w;
        }
        __syncthreads();
    }
#pragma unroll
    for (int i = 0; i < 4; i++) {
        int row = bm0 + ty * 4 + i;
        if (row >= M) continue;
#pragma unroll
        for (int j = 0; j < 4; j++) {
            int col = bn0 + tx * 4 + j;
            if (col >= Npad) continue;
            float v = 0.f;
            if (col < Ntrue) {
                v = acc[i][j];
                if (bias) v += bias[col];
                if (relu) v = fmaxf(v, 0.f);
            }
            C[(size_t)row * Npad + col] = v;
        }
    }
}

// ---------------- GCN propagation: p = A_norm h + dinv^2 * h -------------------
// warp per node; C4 float4-chunks of 128 floats each (F = C4*128)
template <int C4>
__global__ void k_agg4(const float* __restrict__ h, float* __restrict__ p) {
    int v = blockIdx.x * 8 + (threadIdx.x >> 5);
    if (v >= NN) return;
    int lane = threadIdx.x & 31;
    constexpr int F = C4 * 128;
    float dv = g_dinv[v];
    const float4* hv = (const float4*)(h + (size_t)v * F);
    float4 acc[C4];
    float s2 = dv * dv;
#pragma unroll
    for (int i = 0; i < C4; i++) {
        float4 t = hv[lane + i * 32];
        acc[i] = make_float4(t.x * s2, t.y * s2, t.z * s2, t.w * s2);
    }
    int e = g_rowptr[v], end = g_rowptr[v + 1];
    for (; e < end; e++) {
        int s = g_colsrc[e];
        if ((unsigned)s >= NN) continue;
        float nrm = dv * g_dinv[s];
        const float4* hs = (const float4*)(h + (size_t)s * F);
#pragma unroll
        for (int i = 0; i < C4; i++) {
            float4 t = hs[lane + i * 32];
            acc[i].x += nrm * t.x; acc[i].y += nrm * t.y;
            acc[i].z += nrm * t.z; acc[i].w += nrm * t.w;
        }
    }
    float4* pv = (float4*)(p + (size_t)v * F);
#pragma unroll
    for (int i = 0; i < C4; i++) pv[lane + i * 32] = acc[i];
}

// F = 64 variant (float2 per lane)
__global__ void k_agg_f2(const float* __restrict__ h, float* __restrict__ p) {
    int v = blockIdx.x * 8 + (threadIdx.x >> 5);
    if (v >= NN) return;
    int lane = threadIdx.x & 31;
    float dv = g_dinv[v];
    float2 a = ((const float2*)(h + (size_t)v * 64))[lane];
    float s2 = dv * dv;
    a.x *= s2; a.y *= s2;
    int e = g_rowptr[v], end = g_rowptr[v + 1];
    for (; e < end; e++) {
        int s = g_colsrc[e];
        if ((unsigned)s >= NN) continue;
        float nrm = dv * g_dinv[s];
        float2 t = ((const float2*)(h + (size_t)s * 64))[lane];
        a.x += nrm * t.x; a.y += nrm * t.y;
    }
    ((float2*)(p + (size_t)v * 64))[lane] = a;
}

// ---------------- softmax over 50 logits (+ final bias) ------------------------
__global__ void k_softmax(const float* __restrict__ p, const float* __restrict__ b,
                          float* __restrict__ out) {
    int v = blockIdx.x * 8 + (threadIdx.x >> 5);
    if (v >= NN) return;
    int lane = threadIdx.x & 31;
    const float* pv = p + (size_t)v * 64;
    float v0 = pv[lane] + b[lane];                    // lane < 32 < 50 always valid
    bool has1 = (lane + 32) < 50;
    float v1 = has1 ? (pv[lane + 32] + b[lane + 32]) : -1e30f;
    float m = fmaxf(v0, v1);
#pragma unroll
    for (int off = 16; off >= 1; off >>= 1)
        m = fmaxf(m, __shfl_xor_sync(0xffffffffu, m, off));
    float e0 = __expf(v0 - m);
    float e1 = has1 ? __expf(v1 - m) : 0.f;
    float s = e0 + e1;
#pragma unroll
    for (int off = 16; off >= 1; off >>= 1)
        s += __shfl_xor_sync(0xffffffffu, s, off);
    float inv = 1.0f / s;
    out[(size_t)v * 50 + lane] = e0 * inv;
    if (has1) out[(size_t)v * 50 + lane + 32] = e1 * inv;
}

// ---------------- launch ------------------------------------------------------
static inline void* sym(const void* s) {
    void* p = nullptr;
    cudaGetSymbolAddress(&p, s);
    return p;
}

extern "C" void kernel_launch(void* const* d_in, const int* in_sizes, int n_in,
                              void* d_out, int out_size) {
    const float* x   = (const float*)d_in[0];
    const int*   ei  = (const int*)d_in[1];
    const float* w1  = (const float*)d_in[2];
    const float* b1  = (const float*)d_in[3];
    const float* w2  = (const float*)d_in[4];
    const float* b2  = (const float*)d_in[5];
    const float* w3  = (const float*)d_in[6];
    const float* b3  = (const float*)d_in[7];
    const float* g1w = (const float*)d_in[8];
    const float* g1b = (const float*)d_in[9];
    const float* g2w = (const float*)d_in[10];
    const float* g2b = (const float*)d_in[11];
    const float* g3w = (const float*)d_in[12];
    const float* g3b = (const float*)d_in[13];
    float* out = (float*)d_out;

    float* h32  = (float*)sym(g_h32);
    float* h64  = (float*)sym(g_h64);
    float* h128 = (float*)sym(g_h128);
    float* p128 = (float*)sym(g_p128);
    float* h256 = (float*)sym(g_h256);
    float* p256 = (float*)sym(g_p256);
    float* h512 = (float*)sym(g_h512);
    float* t64  = (float*)sym(g_t64);
    float* p64  = (float*)sym(g_p64);

    // degree + CSR
    k_zero_cnt<<<(NN + 255) / 256, 256>>>();
    k_count<<<(NE + 255) / 256, 256>>>(ei);
    k_dinv<<<(NN + 255) / 256, 256>>>();
    k_scan1<<<NBLK, 1024>>>();
    k_scan2<<<1, 64>>>();
    k_scan3<<<(NN + 255) / 256, 256>>>();
    k_scatter<<<(NE + 255) / 256, 256>>>(ei);

    auto grid = [](int M, int Np) { return dim3((M + 63) / 64, (Np + 63) / 64); };

    // MLP
    k_gemm<<<grid(NN, 32), 256>>>(x,    w1, b1, h32,  NN, 3,   32,  32,  1);
    k_gemm<<<grid(NN, 64), 256>>>(h32,  w2, b2, h64,  NN, 32,  64,  64,  1);
    k_gemm<<<grid(NN, 128), 256>>>(h64, w3, b3, h128, NN, 64,  128, 128, 1);

    // GCN1: propagate at 128, then 128->256 matmul + bias + relu
    k_agg4<1><<<(NN + 7) / 8, 256>>>(h128, p128);
    k_gemm<<<grid(NN, 256), 256>>>(p128, g1w, g1b, h256, NN, 128, 256, 256, 1);

    // GCN2: propagate at 256, then 256->512
    k_agg4<2><<<(NN + 7) / 8, 256>>>(h256, p256);
    k_gemm<<<grid(NN, 512), 256>>>(p256, g2w, g2b, h512, NN, 256, 512, 512, 1);

    // GCN3: matmul 512->50 (padded to 64, no bias) first, then propagate at 64
    k_gemm<<<grid(NN, 64), 256>>>(h512, g3w, nullptr, t64, NN, 512, 50, 64, 0);
    k_agg_f2<<<(NN + 7) / 8, 256>>>(t64, p64);

    // softmax(p + g3b)
    k_softmax<<<(NN + 7) / 8, 256>>>(p64, g3b, out);
}